// round 12
// baseline (speedup 1.0000x reference)
#include <cuda_runtime.h>
#include <cstdint>

#define BATCH 8
#define SEQ   2048
#define DIM   1024
#define UDIM  1024

#define BM_ 128          // CTA tile M
#define BN_ 128          // CTA tile N
#define KC  32           // K per stage (32 floats = 128B row)
#define NSTG 3
#define NTH 256
#define STAGE_A 16384    // 128 rows x 128B
#define STAGE_B 16384    // 128 rows x 128B
#define STAGE_BYTES (STAGE_A + STAGE_B)
#define SMEM_BYTES (NSTG * STAGE_BYTES)     // 96KB -> 2 CTAs/SM

// ---------------- scratch (no allocations allowed) ----------------
__device__ float g_metricT[(size_t)DIM*UDIM];
__device__ float g_Wqr[(size_t)DIM*UDIM];
__device__ float g_WqmT[(size_t)DIM*UDIM];
__device__ float g_WkT[(size_t)DIM*UDIM];
__device__ float g_WvT[(size_t)DIM*UDIM];
__device__ float g_bqm[UDIM];
__device__ float g_Q [(size_t)BATCH*SEQ*UDIM];
__device__ float g_Kt[(size_t)BATCH*SEQ*UDIM];
__device__ float g_VT[(size_t)BATCH*SEQ*UDIM];
__device__ float g_S [(size_t)BATCH*SEQ*SEQ];

// ---------------- helpers ----------------
__device__ __forceinline__ float rnd(float x) {         // fp32 -> tf32-representable (rna)
    uint32_t r; asm("cvt.rna.tf32.f32 %0, %1;" : "=r"(r) : "f"(x));
    return __uint_as_float(r);
}
__device__ __forceinline__ uint32_t s2u(const void* p) {
    return (uint32_t)__cvta_generic_to_shared(p);
}
__device__ __forceinline__ void cp16(uint32_t s, const void* g) {
    asm volatile("cp.async.cg.shared.global [%0], [%1], 16;" :: "r"(s), "l"(g) : "memory");
}
__device__ __forceinline__ void cp_commit() {
    asm volatile("cp.async.commit_group;" ::: "memory");
}
__device__ __forceinline__ void cp_wait(int n) {
    if (n <= 0)      asm volatile("cp.async.wait_group 0;" ::: "memory");
    else if (n == 1) asm volatile("cp.async.wait_group 1;" ::: "memory");
    else             asm volatile("cp.async.wait_group 2;" ::: "memory");
}
__device__ __forceinline__ void ldsm4(uint32_t* r, uint32_t a) {
    asm volatile("ldmatrix.sync.aligned.m8n8.x4.shared.b16 {%0,%1,%2,%3}, [%4];"
        : "=r"(r[0]), "=r"(r[1]), "=r"(r[2]), "=r"(r[3]) : "r"(a));
}
__device__ __forceinline__ void mma8(float* c, const uint32_t* a, const uint32_t* b) {
    asm("mma.sync.aligned.m16n8k8.row.col.f32.tf32.tf32.f32 "
        "{%0,%1,%2,%3}, {%4,%5,%6,%7}, {%8,%9}, {%0,%1,%2,%3};"
        : "+f"(c[0]), "+f"(c[1]), "+f"(c[2]), "+f"(c[3])
        : "r"(a[0]), "r"(a[1]), "r"(a[2]), "r"(a[3]), "r"(b[0]), "r"(b[1]));
}
// SW128 swizzle of (row, byte-in-row): byte chunk bits [4:6] XOR row bits [0:2]
__device__ __forceinline__ int swz(int row, int b) {
    return row * 128 + (b ^ ((row * 16) & 0x70));
}

// ---------------- NT GEMM: C[m,n] = scale * sum_k A[m,k]*B[n,k] (+bias) ----------------
// A, B k-major (k contiguous). ldmatrix-fed m16n8k8 tf32 mma, 3-stage cp.async.
// CTA 128x128, warp 64x32 (8 warps: 2 in m, 4 in n), 2 CTAs/SM.
// roundA: cvt.rna A-fragments after ldmatrix (A may be raw fp32).
// storeT: write C transposed into [b][N][SEQ] (b = m-row >> 11).
__global__ void __launch_bounds__(NTH, 2)
mma_gemm(const float* __restrict__ A, const float* __restrict__ B,
         const float* __restrict__ bias, float* __restrict__ C,
         int N, int K, int ldA, int ldB, int ldC,
         long strA, long strB, long strC,
         float scale, int doRound, int causalK, int causalMask,
         int roundA, int storeT)
{
    const int m0 = blockIdx.y * BM_;
    const int n0 = blockIdx.x * BN_;
    if (causalMask && n0 > m0) return;             // fully-masked scores tile

    extern __shared__ char smem[];
    const uint32_t sbase = s2u(smem);
    const int tid = threadIdx.x, lane = tid & 31, w = tid >> 5;
    const int wm0 = (w >> 2) * 64;                 // 2 warps in m
    const int wn0 = (w & 3) * 32;                  // 4 warps in n

    const float* Ag = A + (size_t)blockIdx.z * strA;
    const float* Bg = B + (size_t)blockIdx.z * strB;
    float*       Cg = C + (size_t)blockIdx.z * strC;

    int Kc = K / KC;
    if (causalK) { int kl = (m0 + BM_) / KC; if (kl < Kc) Kc = kl; }

    uint32_t stA[NSTG], stB[NSTG];
#pragma unroll
    for (int s = 0; s < NSTG; s++) { stA[s] = sbase + s * STAGE_BYTES; stB[s] = stA[s] + STAGE_A; }

    // ---- cp.async fill: thread -> (row r0 + 32q, 16B chunk b16) ----
    const int r0  = tid >> 3;            // 0..31
    const int b16 = (tid & 7) * 16;
    auto fill = [&](int kc, int s) {
        const char* asrc = (const char*)(Ag + (size_t)(m0 + r0) * ldA + kc * KC) + b16;
        const size_t aStep = (size_t)32 * ldA * 4;
        uint32_t ab = stA[s];
#pragma unroll
        for (int q = 0; q < 4; q++) { cp16(ab + swz(r0 + q * 32, b16), asrc); asrc += aStep; }
        const char* bsrc = (const char*)(Bg + (size_t)(n0 + r0) * ldB + kc * KC) + b16;
        const size_t bStep = (size_t)32 * ldB * 4;
        uint32_t bb = stB[s];
#pragma unroll
        for (int q = 0; q < 4; q++) { cp16(bb + swz(r0 + q * 32, b16), bsrc); bsrc += bStep; }
        cp_commit();
    };

    // ---- per-thread ldmatrix address components ----
    int aoff[4], amask[4];
#pragma unroll
    for (int im = 0; im < 4; im++) {
        int row = wm0 + im * 16 + (lane & 7) + ((lane >> 3) & 1) * 8;
        aoff[im] = row * 128; amask[im] = (row * 16) & 0x70;
    }
    const int akb = ((lane >> 4) & 1) * 16;
    int boff[2], bmask[2];
#pragma unroll
    for (int ip = 0; ip < 2; ip++) {
        int row = wn0 + ip * 16 + (lane & 7) + ((lane >> 4) & 1) * 8;
        boff[ip] = row * 128; bmask[ip] = (row * 16) & 0x70;
    }
    const int bkb = ((lane >> 3) & 1) * 16;

    float acc[4][4][4];
#pragma unroll
    for (int im = 0; im < 4; im++)
#pragma unroll
        for (int in = 0; in < 4; in++) {
            acc[im][in][0] = 0.f; acc[im][in][1] = 0.f;
            acc[im][in][2] = 0.f; acc[im][in][3] = 0.f;
        }

    fill(0, 0); fill(1, 1);

    for (int i = 0; i < Kc; i++) {
        __syncthreads();                                  // prev iter's reads done
        if (i + 2 < Kc) fill(i + 2, (i + 2) % NSTG);
        int pend = Kc - 1 - i; if (pend > 2) pend = 2;
        cp_wait(pend);
        __syncthreads();                                  // stage i visible to all

        const uint32_t sa = stA[i % NSTG], sb = stB[i % NSTG];
#pragma unroll
        for (int ks = 0; ks < 4; ks++) {
            uint32_t af[4][4], bf[2][4];
            const int kbA = ks * 32 + akb, kbB = ks * 32 + bkb;
#pragma unroll
            for (int im = 0; im < 4; im++) ldsm4(af[im], sa + aoff[im] + (kbA ^ amask[im]));
#pragma unroll
            for (int ip = 0; ip < 2; ip++) ldsm4(bf[ip], sb + boff[ip] + (kbB ^ bmask[ip]));
            if (roundA) {                                  // raw fp32 A -> tf32 (rna)
#pragma unroll
                for (int im = 0; im < 4; im++)
#pragma unroll
                    for (int rr = 0; rr < 4; rr++)
                        af[im][rr] = __float_as_uint(rnd(__uint_as_float(af[im][rr])));
            }
#pragma unroll
            for (int im = 0; im < 4; im++)
#pragma unroll
                for (int in = 0; in < 4; in++)
                    mma8(acc[im][in], af[im], &bf[in >> 1][(in & 1) * 2]);
        }
    }

    // ---- epilogue ----
#pragma unroll
    for (int im = 0; im < 4; im++)
#pragma unroll
        for (int in = 0; in < 4; in++) {
            const int i0 = m0 + wm0 + im * 16 + (lane >> 2);
            const int j0 = n0 + wn0 + in * 8 + (lane & 3) * 2;
            float v0 = acc[im][in][0] * scale, v1 = acc[im][in][1] * scale;
            float v2 = acc[im][in][2] * scale, v3 = acc[im][in][3] * scale;
            if (bias) {
                const float b0 = bias[j0], b1 = bias[j0 + 1];
                v0 += b0; v1 += b1; v2 += b0; v3 += b1;
            }
            if (causalMask) {
                if (j0     > i0)     v0 = -1e9f;
                if (j0 + 1 > i0)     v1 = -1e9f;
                if (j0     > i0 + 8) v2 = -1e9f;
                if (j0 + 1 > i0 + 8) v3 = -1e9f;
            }
            if (doRound) { v0 = rnd(v0); v1 = rnd(v1); v2 = rnd(v2); v3 = rnd(v3); }
            if (storeT) {
                // C^T[b][j][t]: b from global m-row, t = token within batch
                const int b = i0 >> 11;                    // SEQ = 2048
                const int t = i0 & (SEQ - 1);
                float* vt = Cg + ((size_t)b * N + j0) * SEQ + t;
                vt[0] = v0; vt[SEQ] = v1; vt[8] = v2; vt[SEQ + 8] = v3;
            } else {
                *reinterpret_cast<float2*>(Cg + (size_t)i0 * ldC + j0) = make_float2(v0, v1);
                *reinterpret_cast<float2*>(Cg + (size_t)(i0 + 8) * ldC + j0) = make_float2(v2, v3);
            }
        }
}

// ---------------- aux kernels ----------------
__global__ void round4(const float4* __restrict__ x, float4* __restrict__ y, size_t n4) {
    size_t i = (size_t)blockIdx.x * blockDim.x + threadIdx.x;
    const size_t st = (size_t)gridDim.x * blockDim.x;
    for (; i < n4; i += st) {
        float4 v = x[i];
        v.x = rnd(v.x); v.y = rnd(v.y); v.z = rnd(v.z); v.w = rnd(v.w);
        y[i] = v;
    }
}

// dst[Nc, Mr] = rnd(src[Mr, Nc])^T
__global__ void transpose_round(const float* __restrict__ src, float* __restrict__ dst,
                                int Mr, int Nc) {
    __shared__ float t[32][33];
    int x = blockIdx.x * 32 + threadIdx.x;
    int y = blockIdx.y * 32 + threadIdx.y;
#pragma unroll
    for (int j = 0; j < 32; j += 8)
        t[threadIdx.y + j][threadIdx.x] = rnd(src[(size_t)(y + j) * Nc + x]);
    __syncthreads();
    x = blockIdx.y * 32 + threadIdx.x;
    y = blockIdx.x * 32 + threadIdx.y;
#pragma unroll
    for (int j = 0; j < 32; j += 8)
        dst[(size_t)(y + j) * Mr + x] = t[threadIdx.x][threadIdx.y + j];
}

// warp-per-row causal softmax, register-cached: one read + one write.
// Processes the full 128-aligned tile band; masked entries (-1e9) become exact 0,
// which also provides the zero-fill the PV GEMM's k-limit relies on.
__global__ void __launch_bounds__(256)
softmax_warp(float* __restrict__ S) {
    const int lane = threadIdx.x & 31;
    const int i = blockIdx.x * 8 + (threadIdx.x >> 5);
    const int b = blockIdx.y;
    float4* row = reinterpret_cast<float4*>(S + ((size_t)b * SEQ + i) * SEQ);
    const int nc = (((i >> 7) + 1) << 7) >> 2;   // float4 chunks in this row's band

    float4 v[16];
    float mx = -3.0e38f;
#pragma unroll
    for (int c = 0; c < 16; c++) {
        const int idx = lane + c * 32;
        if (idx < nc) {
            v[c] = row[idx];
            mx = fmaxf(mx, fmaxf(fmaxf(v[c].x, v[c].y), fmaxf(v[c].z, v[c].w)));
        }
    }
#pragma unroll
    for (int o = 16; o; o >>= 1) mx = fmaxf(mx, __shfl_xor_sync(0xFFFFFFFFu, mx, o));

    float sum = 0.f;
#pragma unroll
    for (int c = 0; c < 16; c++) {
        const int idx = lane + c * 32;
        if (idx < nc) {
            v[c].x = __expf(v[c].x - mx); v[c].y = __expf(v[c].y - mx);
            v[c].z = __expf(v[c].z - mx); v[c].w = __expf(v[c].w - mx);
            sum += (v[c].x + v[c].y) + (v[c].z + v[c].w);
        }
    }
#pragma unroll
    for (int o = 16; o; o >>= 1) sum += __shfl_xor_sync(0xFFFFFFFFu, sum, o);
    const float inv = 1.f / sum;

#pragma unroll
    for (int c = 0; c < 16; c++) {
        const int idx = lane + c * 32;
        if (idx < nc) {
            v[c].x = rnd(v[c].x * inv); v[c].y = rnd(v[c].y * inv);
            v[c].z = rnd(v[c].z * inv); v[c].w = rnd(v[c].w * inv);
            row[idx] = v[c];
        }
    }
}

__global__ void bias_metric(const float* __restrict__ bq, const float* __restrict__ metric,
                            float* __restrict__ bqm) {
    const int v = blockIdx.x * blockDim.x + threadIdx.x;
    if (v >= UDIM) return;
    float s = 0.f;
    for (int u = 0; u < UDIM; u++) s = fmaf(bq[u], metric[(size_t)u * UDIM + v], s);
    bqm[v] = s;
}

// ---------------- launch ----------------
extern "C" void kernel_launch(void* const* d_in, const int* in_sizes, int n_in,
                              void* d_out, int out_size)
{
    (void)in_sizes; (void)n_in; (void)out_size;
    const float* X1     = (const float*)d_in[0];
    const float* X2     = (const float*)d_in[1];
    const float* Wq     = (const float*)d_in[2];
    const float* bq     = (const float*)d_in[3];
    const float* Wk     = (const float*)d_in[4];
    const float* bk     = (const float*)d_in[5];
    const float* Wv     = (const float*)d_in[6];
    const float* bv     = (const float*)d_in[7];
    const float* metric = (const float*)d_in[8];
    float* out = (float*)d_out;

    cudaFuncSetAttribute(mma_gemm, cudaFuncAttributeMaxDynamicSharedMemorySize, SMEM_BYTES);

    void* p;
    cudaGetSymbolAddress(&p, g_metricT); float* dMT  = (float*)p;
    cudaGetSymbolAddress(&p, g_Wqr);     float* dWqr = (float*)p;
    cudaGetSymbolAddress(&p, g_WqmT);    float* dWqm = (float*)p;
    cudaGetSymbolAddress(&p, g_WkT);     float* dWkT = (float*)p;
    cudaGetSymbolAddress(&p, g_WvT);     float* dWvT = (float*)p;
    cudaGetSymbolAddress(&p, g_bqm);     float* dbqm = (float*)p;
    cudaGetSymbolAddress(&p, g_Q);       float* dQ   = (float*)p;
    cudaGetSymbolAddress(&p, g_Kt);      float* dK   = (float*)p;
    cudaGetSymbolAddress(&p, g_VT);      float* dVT  = (float*)p;
    cudaGetSymbolAddress(&p, g_S);       float* dS   = (float*)p;

    const int M = BATCH * SEQ;                 // 16384
    dim3 blk(NTH), t8(32, 8);

    // weight-side prep only (X1/X2 are rounded in-fragment inside the GEMM)
    round4<<<256, 256>>>((const float4*)Wq, (float4*)dWqr, (size_t)DIM * UDIM / 4);
    transpose_round<<<dim3(32, 32, 1), t8>>>(metric, dMT, DIM, UDIM);
    transpose_round<<<dim3(32, 32, 1), t8>>>(Wk, dWkT, DIM, UDIM);
    transpose_round<<<dim3(32, 32, 1), t8>>>(Wv, dWvT, DIM, UDIM);
    bias_metric<<<UDIM / 256, 256>>>(bq, metric, dbqm);

    // WqmT[v,d] = sum_u metricT[v,u] * Wq[d,u]  ( = (Wq@metric)^T ), rounded
    mma_gemm<<<dim3(DIM / BN_, UDIM / BM_, 1), blk, SMEM_BYTES>>>(
        dMT, dWqr, nullptr, dWqm, DIM, UDIM, UDIM, UDIM, DIM,
        0, 0, 0, 1.f, 1, 0, 0, 0, 0);

    // projections: A = raw X (fragment-rounded), outputs rounded
    mma_gemm<<<dim3(UDIM / BN_, M / BM_, 1), blk, SMEM_BYTES>>>(
        X1, dWqm, dbqm, dQ, UDIM, DIM, DIM, DIM, UDIM,
        0, 0, 0, 1.f, 1, 0, 0, 1, 0);
    mma_gemm<<<dim3(UDIM / BN_, M / BM_, 1), blk, SMEM_BYTES>>>(
        X2, dWkT, bk, dK, UDIM, DIM, DIM, DIM, UDIM,
        0, 0, 0, 1.f, 1, 0, 0, 1, 0);
    // V projection stores directly transposed into g_VT[b][v][token]
    mma_gemm<<<dim3(UDIM / BN_, M / BM_, 1), blk, SMEM_BYTES>>>(
        X2, dWvT, bv, dVT, UDIM, DIM, DIM, DIM, 0,
        0, 0, 0, 1.f, 1, 0, 0, 1, 1);

    // causal scores (fully-masked tiles early-return; diagonal tiles masked in epilogue)
    mma_gemm<<<dim3(SEQ / BN_, SEQ / BM_, BATCH), blk, SMEM_BYTES>>>(
        dQ, dK, nullptr, dS, SEQ, UDIM, UDIM, UDIM, SEQ,
        (long)SEQ * UDIM, (long)SEQ * UDIM, (long)SEQ * SEQ,
        1.0f / 32.0f, 0, 0, 1, 0, 0);

    softmax_warp<<<dim3(SEQ / 8, BATCH), 256>>>(dS);

    // O = P @ V  (k-limited by causality at 128 granularity; final output, no rounding)
    mma_gemm<<<dim3(UDIM / BN_, SEQ / BM_, BATCH), blk, SMEM_BYTES>>>(
        dS, dVT, nullptr, out, UDIM, SEQ, SEQ, SEQ, UDIM,
        (long)SEQ * SEQ, (long)SEQ * UDIM, (long)SEQ * UDIM,
        1.f, 0, 1, 0, 0, 0);
}

// round 13
// speedup vs baseline: 1.0751x; 1.0751x over previous
#include <cuda_runtime.h>
#include <cstdint>

#define BATCH 8
#define SEQ   2048
#define DIM   1024
#define UDIM  1024

#define BM_ 128          // CTA tile M
#define BN_ 128          // CTA tile N
#define KC  32           // K per stage (32 floats = 128B row)
#define NSTG 3
#define NTH 256
#define STAGE_A 16384    // 128 rows x 128B
#define STAGE_B 16384    // 128 rows x 128B
#define STAGE_BYTES (STAGE_A + STAGE_B)
#define SMEM_BYTES (NSTG * STAGE_BYTES)     // 96KB -> 2 CTAs/SM

// ---------------- scratch (no allocations allowed) ----------------
__device__ float g_metricT[(size_t)DIM*UDIM];
__device__ float g_Wqr[(size_t)DIM*UDIM];
__device__ float g_WqmT[(size_t)DIM*UDIM];
__device__ float g_WkT[(size_t)DIM*UDIM];
__device__ float g_WvT[(size_t)DIM*UDIM];
__device__ float g_bqm[UDIM];
__device__ float g_X1[(size_t)BATCH*SEQ*DIM];
__device__ float g_X2[(size_t)BATCH*SEQ*DIM];
__device__ float g_Q [(size_t)BATCH*SEQ*UDIM];
__device__ float g_Kt[(size_t)BATCH*SEQ*UDIM];
__device__ float g_VT[(size_t)BATCH*SEQ*UDIM];
__device__ float g_S [(size_t)BATCH*SEQ*SEQ];

// ---------------- helpers ----------------
__device__ __forceinline__ float rnd(float x) {         // fp32 -> tf32-representable (rna)
    uint32_t r; asm("cvt.rna.tf32.f32 %0, %1;" : "=r"(r) : "f"(x));
    return __uint_as_float(r);
}
__device__ __forceinline__ uint32_t s2u(const void* p) {
    return (uint32_t)__cvta_generic_to_shared(p);
}
__device__ __forceinline__ void cp16(uint32_t s, const void* g) {
    asm volatile("cp.async.cg.shared.global [%0], [%1], 16;" :: "r"(s), "l"(g) : "memory");
}
__device__ __forceinline__ void cp_commit() {
    asm volatile("cp.async.commit_group;" ::: "memory");
}
__device__ __forceinline__ void cp_wait(int n) {
    if (n <= 0)      asm volatile("cp.async.wait_group 0;" ::: "memory");
    else if (n == 1) asm volatile("cp.async.wait_group 1;" ::: "memory");
    else             asm volatile("cp.async.wait_group 2;" ::: "memory");
}
__device__ __forceinline__ void ldsm4(uint32_t* r, uint32_t a) {
    asm volatile("ldmatrix.sync.aligned.m8n8.x4.shared.b16 {%0,%1,%2,%3}, [%4];"
        : "=r"(r[0]), "=r"(r[1]), "=r"(r[2]), "=r"(r[3]) : "r"(a));
}
__device__ __forceinline__ void mma8(float* c, const uint32_t* a, const uint32_t* b) {
    asm("mma.sync.aligned.m16n8k8.row.col.f32.tf32.tf32.f32 "
        "{%0,%1,%2,%3}, {%4,%5,%6,%7}, {%8,%9}, {%0,%1,%2,%3};"
        : "+f"(c[0]), "+f"(c[1]), "+f"(c[2]), "+f"(c[3])
        : "r"(a[0]), "r"(a[1]), "r"(a[2]), "r"(a[3]), "r"(b[0]), "r"(b[1]));
}
// SW128 swizzle of (row, byte-in-row): byte chunk bits [4:6] XOR row bits [0:2]
__device__ __forceinline__ int swz(int row, int b) {
    return row * 128 + (b ^ ((row * 16) & 0x70));
}

// ---------------- NT GEMM: C[m,n] = scale * sum_k A[m,k]*B[n,k] (+bias) ----------------
// A, B k-major (k contiguous), pre-rounded to tf32. ldmatrix-fed m16n8k8 tf32 mma,
// 3-stage cp.async. CTA 128x128, warp 64x32 (8 warps: 2m x 4n), 2 CTAs/SM.
// causalK: limit k to the causal band; m-tile order reversed (heaviest first).
// storeT: write C transposed into [b][N][SEQ] (b = m-row >> 11).
__global__ void __launch_bounds__(NTH, 2)
mma_gemm(const float* __restrict__ A, const float* __restrict__ B,
         const float* __restrict__ bias, float* __restrict__ C,
         int N, int K, int ldA, int ldB, int ldC,
         long strA, long strB, long strC,
         float scale, int doRound, int causalK, int causalMask, int storeT)
{
    const int bm = causalK ? (gridDim.y - 1 - blockIdx.y) : blockIdx.y;  // LPT order
    const int m0 = bm * BM_;
    const int n0 = blockIdx.x * BN_;
    if (causalMask && n0 > m0) return;             // fully-masked scores tile

    extern __shared__ char smem[];
    const uint32_t sbase = s2u(smem);
    const int tid = threadIdx.x, lane = tid & 31, w = tid >> 5;
    const int wm0 = (w >> 2) * 64;                 // 2 warps in m
    const int wn0 = (w & 3) * 32;                  // 4 warps in n

    const float* Ag = A + (size_t)blockIdx.z * strA;
    const float* Bg = B + (size_t)blockIdx.z * strB;
    float*       Cg = C + (size_t)blockIdx.z * strC;

    int Kc = K / KC;
    if (causalK) { int kl = (m0 + BM_) / KC; if (kl < Kc) Kc = kl; }

    uint32_t stA[NSTG], stB[NSTG];
#pragma unroll
    for (int s = 0; s < NSTG; s++) { stA[s] = sbase + s * STAGE_BYTES; stB[s] = stA[s] + STAGE_A; }

    // ---- cp.async fill: thread -> (row r0 + 32q, 16B chunk b16) ----
    const int r0  = tid >> 3;            // 0..31
    const int b16 = (tid & 7) * 16;
    auto fill = [&](int kc, int s) {
        const char* asrc = (const char*)(Ag + (size_t)(m0 + r0) * ldA + kc * KC) + b16;
        const size_t aStep = (size_t)32 * ldA * 4;
        uint32_t ab = stA[s];
#pragma unroll
        for (int q = 0; q < 4; q++) { cp16(ab + swz(r0 + q * 32, b16), asrc); asrc += aStep; }
        const char* bsrc = (const char*)(Bg + (size_t)(n0 + r0) * ldB + kc * KC) + b16;
        const size_t bStep = (size_t)32 * ldB * 4;
        uint32_t bb = stB[s];
#pragma unroll
        for (int q = 0; q < 4; q++) { cp16(bb + swz(r0 + q * 32, b16), bsrc); bsrc += bStep; }
        cp_commit();
    };

    // ---- per-thread ldmatrix address components ----
    int aoff[4], amask[4];
#pragma unroll
    for (int im = 0; im < 4; im++) {
        int row = wm0 + im * 16 + (lane & 7) + ((lane >> 3) & 1) * 8;
        aoff[im] = row * 128; amask[im] = (row * 16) & 0x70;
    }
    const int akb = ((lane >> 4) & 1) * 16;
    int boff[2], bmask[2];
#pragma unroll
    for (int ip = 0; ip < 2; ip++) {
        int row = wn0 + ip * 16 + (lane & 7) + ((lane >> 4) & 1) * 8;
        boff[ip] = row * 128; bmask[ip] = (row * 16) & 0x70;
    }
    const int bkb = ((lane >> 3) & 1) * 16;

    float acc[4][4][4];
#pragma unroll
    for (int im = 0; im < 4; im++)
#pragma unroll
        for (int in = 0; in < 4; in++) {
            acc[im][in][0] = 0.f; acc[im][in][1] = 0.f;
            acc[im][in][2] = 0.f; acc[im][in][3] = 0.f;
        }

    fill(0, 0); fill(1, 1);

    for (int i = 0; i < Kc; i++) {
        __syncthreads();                                  // prev iter's reads done
        if (i + 2 < Kc) fill(i + 2, (i + 2) % NSTG);
        int pend = Kc - 1 - i; if (pend > 2) pend = 2;
        cp_wait(pend);
        __syncthreads();                                  // stage i visible to all

        const uint32_t sa = stA[i % NSTG], sb = stB[i % NSTG];
#pragma unroll
        for (int ks = 0; ks < 4; ks++) {
            uint32_t af[4][4], bf[2][4];
            const int kbA = ks * 32 + akb, kbB = ks * 32 + bkb;
#pragma unroll
            for (int im = 0; im < 4; im++) ldsm4(af[im], sa + aoff[im] + (kbA ^ amask[im]));
#pragma unroll
            for (int ip = 0; ip < 2; ip++) ldsm4(bf[ip], sb + boff[ip] + (kbB ^ bmask[ip]));
#pragma unroll
            for (int im = 0; im < 4; im++)
#pragma unroll
                for (int in = 0; in < 4; in++)
                    mma8(acc[im][in], af[im], &bf[in >> 1][(in & 1) * 2]);
        }
    }

    // ---- epilogue ----
#pragma unroll
    for (int im = 0; im < 4; im++)
#pragma unroll
        for (int in = 0; in < 4; in++) {
            const int i0 = m0 + wm0 + im * 16 + (lane >> 2);
            const int j0 = n0 + wn0 + in * 8 + (lane & 3) * 2;
            float v0 = acc[im][in][0] * scale, v1 = acc[im][in][1] * scale;
            float v2 = acc[im][in][2] * scale, v3 = acc[im][in][3] * scale;
            if (bias) {
                const float b0 = bias[j0], b1 = bias[j0 + 1];
                v0 += b0; v1 += b1; v2 += b0; v3 += b1;
            }
            if (causalMask) {
                if (j0     > i0)     v0 = -1e9f;
                if (j0 + 1 > i0)     v1 = -1e9f;
                if (j0     > i0 + 8) v2 = -1e9f;
                if (j0 + 1 > i0 + 8) v3 = -1e9f;
            }
            if (doRound) { v0 = rnd(v0); v1 = rnd(v1); v2 = rnd(v2); v3 = rnd(v3); }
            if (storeT) {
                // C^T[b][j][t]: b from global m-row, t = token within batch
                const int b = i0 >> 11;                    // SEQ = 2048
                const int t = i0 & (SEQ - 1);
                float* vt = Cg + ((size_t)b * N + j0) * SEQ + t;
                vt[0] = v0; vt[SEQ] = v1; vt[8] = v2; vt[SEQ + 8] = v3;
            } else {
                *reinterpret_cast<float2*>(Cg + (size_t)i0 * ldC + j0) = make_float2(v0, v1);
                *reinterpret_cast<float2*>(Cg + (size_t)(i0 + 8) * ldC + j0) = make_float2(v2, v3);
            }
        }
}

// ---------------- aux kernels ----------------
__global__ void round4(const float4* __restrict__ x, float4* __restrict__ y, size_t n4) {
    size_t i = (size_t)blockIdx.x * blockDim.x + threadIdx.x;
    const size_t st = (size_t)gridDim.x * blockDim.x;
    for (; i < n4; i += st) {
        float4 v = x[i];
        v.x = rnd(v.x); v.y = rnd(v.y); v.z = rnd(v.z); v.w = rnd(v.w);
        y[i] = v;
    }
}

// dst[Nc, Mr] = rnd(src[Mr, Nc])^T
__global__ void transpose_round(const float* __restrict__ src, float* __restrict__ dst,
                                int Mr, int Nc) {
    __shared__ float t[32][33];
    int x = blockIdx.x * 32 + threadIdx.x;
    int y = blockIdx.y * 32 + threadIdx.y;
#pragma unroll
    for (int j = 0; j < 32; j += 8)
        t[threadIdx.y + j][threadIdx.x] = rnd(src[(size_t)(y + j) * Nc + x]);
    __syncthreads();
    x = blockIdx.y * 32 + threadIdx.x;
    y = blockIdx.x * 32 + threadIdx.y;
#pragma unroll
    for (int j = 0; j < 32; j += 8)
        dst[(size_t)(y + j) * Mr + x] = t[threadIdx.x][threadIdx.y + j];
}

// warp-per-row causal softmax, register-cached: one read + one write.
// Processes the full 128-aligned tile band; masked entries (-1e9) become exact 0,
// which also provides the zero-fill the PV GEMM's k-limit relies on.
__global__ void __launch_bounds__(256)
softmax_warp(float* __restrict__ S) {
    const int lane = threadIdx.x & 31;
    const int i = blockIdx.x * 8 + (threadIdx.x >> 5);
    const int b = blockIdx.y;
    float4* row = reinterpret_cast<float4*>(S + ((size_t)b * SEQ + i) * SEQ);
    const int nc = (((i >> 7) + 1) << 7) >> 2;   // float4 chunks in this row's band

    float4 v[16];
    float mx = -3.0e38f;
#pragma unroll
    for (int c = 0; c < 16; c++) {
        const int idx = lane + c * 32;
        if (idx < nc) {
            v[c] = row[idx];
            mx = fmaxf(mx, fmaxf(fmaxf(v[c].x, v[c].y), fmaxf(v[c].z, v[c].w)));
        }
    }
#pragma unroll
    for (int o = 16; o; o >>= 1) mx = fmaxf(mx, __shfl_xor_sync(0xFFFFFFFFu, mx, o));

    float sum = 0.f;
#pragma unroll
    for (int c = 0; c < 16; c++) {
        const int idx = lane + c * 32;
        if (idx < nc) {
            v[c].x = __expf(v[c].x - mx); v[c].y = __expf(v[c].y - mx);
            v[c].z = __expf(v[c].z - mx); v[c].w = __expf(v[c].w - mx);
            sum += (v[c].x + v[c].y) + (v[c].z + v[c].w);
        }
    }
#pragma unroll
    for (int o = 16; o; o >>= 1) sum += __shfl_xor_sync(0xFFFFFFFFu, sum, o);
    const float inv = 1.f / sum;

#pragma unroll
    for (int c = 0; c < 16; c++) {
        const int idx = lane + c * 32;
        if (idx < nc) {
            v[c].x = rnd(v[c].x * inv); v[c].y = rnd(v[c].y * inv);
            v[c].z = rnd(v[c].z * inv); v[c].w = rnd(v[c].w * inv);
            row[idx] = v[c];
        }
    }
}

__global__ void bias_metric(const float* __restrict__ bq, const float* __restrict__ metric,
                            float* __restrict__ bqm) {
    const int v = blockIdx.x * blockDim.x + threadIdx.x;
    if (v >= UDIM) return;
    float s = 0.f;
    for (int u = 0; u < UDIM; u++) s = fmaf(bq[u], metric[(size_t)u * UDIM + v], s);
    bqm[v] = s;
}

// ---------------- launch ----------------
extern "C" void kernel_launch(void* const* d_in, const int* in_sizes, int n_in,
                              void* d_out, int out_size)
{
    (void)in_sizes; (void)n_in; (void)out_size;
    const float* X1     = (const float*)d_in[0];
    const float* X2     = (const float*)d_in[1];
    const float* Wq     = (const float*)d_in[2];
    const float* bq     = (const float*)d_in[3];
    const float* Wk     = (const float*)d_in[4];
    const float* bk     = (const float*)d_in[5];
    const float* Wv     = (const float*)d_in[6];
    const float* bv     = (const float*)d_in[7];
    const float* metric = (const float*)d_in[8];
    float* out = (float*)d_out;

    cudaFuncSetAttribute(mma_gemm, cudaFuncAttributeMaxDynamicSharedMemorySize, SMEM_BYTES);

    void* p;
    cudaGetSymbolAddress(&p, g_metricT); float* dMT  = (float*)p;
    cudaGetSymbolAddress(&p, g_Wqr);     float* dWqr = (float*)p;
    cudaGetSymbolAddress(&p, g_WqmT);    float* dWqm = (float*)p;
    cudaGetSymbolAddress(&p, g_WkT);     float* dWkT = (float*)p;
    cudaGetSymbolAddress(&p, g_WvT);     float* dWvT = (float*)p;
    cudaGetSymbolAddress(&p, g_bqm);     float* dbqm = (float*)p;
    cudaGetSymbolAddress(&p, g_X1);      float* dX1  = (float*)p;
    cudaGetSymbolAddress(&p, g_X2);      float* dX2  = (float*)p;
    cudaGetSymbolAddress(&p, g_Q);       float* dQ   = (float*)p;
    cudaGetSymbolAddress(&p, g_Kt);      float* dK   = (float*)p;
    cudaGetSymbolAddress(&p, g_VT);      float* dVT  = (float*)p;
    cudaGetSymbolAddress(&p, g_S);       float* dS   = (float*)p;

    const int M = BATCH * SEQ;                 // 16384
    dim3 blk(NTH), t8(32, 8);

    // operand prep: pre-round X (off the GEMM critical loop), weight transposes
    round4<<<1024, 256>>>((const float4*)X1, (float4*)dX1, (size_t)M * DIM / 4);
    round4<<<1024, 256>>>((const float4*)X2, (float4*)dX2, (size_t)M * DIM / 4);
    round4<<<256, 256>>>((const float4*)Wq, (float4*)dWqr, (size_t)DIM * UDIM / 4);
    transpose_round<<<dim3(32, 32, 1), t8>>>(metric, dMT, DIM, UDIM);
    transpose_round<<<dim3(32, 32, 1), t8>>>(Wk, dWkT, DIM, UDIM);
    transpose_round<<<dim3(32, 32, 1), t8>>>(Wv, dWvT, DIM, UDIM);
    bias_metric<<<UDIM / 256, 256>>>(bq, metric, dbqm);

    // WqmT[v,d] = sum_u metricT[v,u] * Wq[d,u]  ( = (Wq@metric)^T ), rounded
    mma_gemm<<<dim3(DIM / BN_, UDIM / BM_, 1), blk, SMEM_BYTES>>>(
        dMT, dWqr, nullptr, dWqm, DIM, UDIM, UDIM, UDIM, DIM,
        0, 0, 0, 1.f, 1, 0, 0, 0);

    // projections (pre-rounded A), outputs rounded
    mma_gemm<<<dim3(UDIM / BN_, M / BM_, 1), blk, SMEM_BYTES>>>(
        dX1, dWqm, dbqm, dQ, UDIM, DIM, DIM, DIM, UDIM,
        0, 0, 0, 1.f, 1, 0, 0, 0);
    mma_gemm<<<dim3(UDIM / BN_, M / BM_, 1), blk, SMEM_BYTES>>>(
        dX2, dWkT, bk, dK, UDIM, DIM, DIM, DIM, UDIM,
        0, 0, 0, 1.f, 1, 0, 0, 0);
    // V projection stores directly transposed into g_VT[b][v][token]
    mma_gemm<<<dim3(UDIM / BN_, M / BM_, 1), blk, SMEM_BYTES>>>(
        dX2, dWvT, bv, dVT, UDIM, DIM, DIM, DIM, 0,
        0, 0, 0, 1.f, 1, 0, 0, 1);

    // causal scores (fully-masked tiles early-return; diagonal tiles masked in epilogue)
    mma_gemm<<<dim3(SEQ / BN_, SEQ / BM_, BATCH), blk, SMEM_BYTES>>>(
        dQ, dK, nullptr, dS, SEQ, UDIM, UDIM, UDIM, SEQ,
        (long)SEQ * UDIM, (long)SEQ * UDIM, (long)SEQ * SEQ,
        1.0f / 32.0f, 0, 0, 1, 0);

    softmax_warp<<<dim3(SEQ / 8, BATCH), 256>>>(dS);

    // O = P @ V  (k-limited by causality at 128 granularity, heaviest tiles first)
    mma_gemm<<<dim3(UDIM / BN_, SEQ / BM_, BATCH), blk, SMEM_BYTES>>>(
        dS, dVT, nullptr, out, UDIM, SEQ, SEQ, SEQ, UDIM,
        (long)SEQ * SEQ, (long)SEQ * UDIM, (long)SEQ * UDIM,
        1.f, 0, 1, 0, 0);
}